// round 2
// baseline (speedup 1.0000x reference)
#include <cuda_runtime.h>
#include <math.h>
#include <math_constants.h>

#define NMAX 50000
#define EMAX 800000
#define F 64
#define NH 4

// ---------------- scratch (device globals; referenced ONLY from device code) ----------------
__device__ float g_xln[NMAX * F];          // Tx0 (layernormed x)
__device__ float g_tx1[NMAX * F];          // Tx1 = L_hat @ Tx0
__device__ float g_tx2[NMAX * F];          // accum of L_hat @ Tx1 (Tx2 = 2*this - Tx0)
__device__ float g_h[NMAX * F];            // cheb output after leaky
__device__ float g_xh[NMAX * NH * F];      // GAT projected features [N, H, C]
__device__ float g_asrc[NMAX * NH];
__device__ float g_adst[NMAX * NH];
__device__ float g_deg[NMAX];
__device__ float g_dinv[NMAX];
__device__ float g_we[EMAX];               // scaled-Laplacian edge weights
__device__ float g_emax[NMAX * NH];
__device__ float g_denom[NMAX * NH];
__device__ float g_ex[(EMAX + NMAX) * NH]; // exp(e - emax) per (edge-or-loop, head)

// ---------------- helpers ----------------
__device__ __forceinline__ void atomicMaxF(float* addr, float v) {
    int* ai = (int*)addr;
    int old = *ai;
    while (__int_as_float(old) < v) {
        int assumed = old;
        old = atomicCAS(ai, assumed, __float_as_int(v));
        if (old == assumed) break;
    }
}

__device__ __forceinline__ float leaky(float x, float s) {
    return x >= 0.f ? x : s * x;
}

// ---------------- kernels ----------------
__global__ void k_init(float* out, int n) {
    int i = blockIdx.x * blockDim.x + threadIdx.x;
    if (i < n * F) { g_tx1[i] = 0.f; g_tx2[i] = 0.f; out[i] = 0.f; }
    if (i < n)      g_deg[i] = 0.f;
    if (i < n * NH) { g_denom[i] = 0.f; g_emax[i] = -CUDART_INF_F; }
}

// one warp per node; lane handles c and c+32
__global__ void k_ln(const float* __restrict__ x, const float* __restrict__ gamma,
                     const float* __restrict__ beta, int n) {
    int warp = (blockIdx.x * blockDim.x + threadIdx.x) >> 5;
    int lane = threadIdx.x & 31;
    if (warp >= n) return;
    const float* xr = x + (size_t)warp * F;
    float a = xr[lane], b = xr[lane + 32];
    float s = a + b, sq = a * a + b * b;
    #pragma unroll
    for (int o = 16; o; o >>= 1) {
        s  += __shfl_xor_sync(0xffffffffu, s,  o);
        sq += __shfl_xor_sync(0xffffffffu, sq, o);
    }
    float mu  = s * (1.f / 64.f);
    float var = sq * (1.f / 64.f) - mu * mu;
    float r = rsqrtf(var + 1e-5f);
    g_xln[warp * F + lane]      = (a - mu) * r * gamma[lane]      + beta[lane];
    g_xln[warp * F + lane + 32] = (b - mu) * r * gamma[lane + 32] + beta[lane + 32];
}

__global__ void k_deg(const int* __restrict__ src, const float* __restrict__ ea, int e) {
    int i = blockIdx.x * blockDim.x + threadIdx.x;
    if (i < e) atomicAdd(&g_deg[src[i]], ea[i]);
}

__global__ void k_dinv(int n) {
    int i = blockIdx.x * blockDim.x + threadIdx.x;
    if (i < n) {
        float d = g_deg[i];
        g_dinv[i] = d > 0.f ? rsqrtf(d) : 0.f;
    }
}

__global__ void k_we(const int* __restrict__ src, const int* __restrict__ dst,
                     const float* __restrict__ ea, int e) {
    int i = blockIdx.x * blockDim.x + threadIdx.x;
    if (i < e) g_we[i] = -(g_dinv[src[i]] * ea[i] * g_dinv[dst[i]]);
}

// scatter: out[dst] += we * in[src]; one thread per (edge, 4 features).
// phase 0: g_xln -> g_tx1 ; phase 1: g_tx1 -> g_tx2   (buffers chosen DEVICE-side)
__global__ void k_prop(const int* __restrict__ src, const int* __restrict__ dst,
                       int e, int phase) {
    int t = blockIdx.x * blockDim.x + threadIdx.x;
    int i = t >> 4, q = (t & 15) << 2;
    if (i >= e) return;
    const float* in  = phase == 0 ? g_xln : g_tx1;
    float*       outp = phase == 0 ? g_tx1 : g_tx2;
    float w = g_we[i];
    const float4 v = *reinterpret_cast<const float4*>(in + __ldg(&src[i]) * F + q);
    float* o = outp + __ldg(&dst[i]) * F + q;
    atomicAdd(o + 0, w * v.x);
    atomicAdd(o + 1, w * v.y);
    atomicAdd(o + 2, w * v.z);
    atomicAdd(o + 3, w * v.w);
}

// Cheb combine: out = Tx0@W0 + Tx1@W1 + (2*Tx2acc - Tx0)@W2 + b, leaky(0.01)
__global__ void k_cheb(const float* __restrict__ cw, const float* __restrict__ cb, int n) {
    int o = threadIdx.x & 63;
    int node = blockIdx.x * 4 + (threadIdx.x >> 6);
    if (node >= n) return;
    const float* t0 = g_xln + node * F;
    const float* t1 = g_tx1 + node * F;
    const float* t2 = g_tx2 + node * F;
    float acc = 0.f;
    #pragma unroll
    for (int c = 0; c < F; c++) {
        float a0 = t0[c], a1 = t1[c];
        float a2 = 2.f * t2[c] - a0;
        acc = fmaf(a0, cw[c * F + o], acc);
        acc = fmaf(a1, cw[F * F + c * F + o], acc);
        acc = fmaf(a2, cw[2 * F * F + c * F + o], acc);
    }
    acc += cb[o];
    g_h[node * F + o] = leaky(acc, 0.01f);
}

// xh = h @ gat_w  (64 -> 256). block = node, 256 threads = one output column each.
__global__ void k_xw(const float* __restrict__ gw, int n) {
    int node = blockIdx.x;
    int j = threadIdx.x;
    const float* hr = g_h + node * F;
    float acc = 0.f;
    #pragma unroll
    for (int c = 0; c < F; c++)
        acc = fmaf(hr[c], gw[c * (NH * F) + j], acc);
    g_xh[node * (NH * F) + j] = acc;
}

// per-(node, head) attention dot products. block = node, 128 threads = 4 warps.
__global__ void k_att(const float* __restrict__ as, const float* __restrict__ ad, int n) {
    int node = blockIdx.x;
    int h = threadIdx.x >> 5, lane = threadIdx.x & 31;
    float x1 = g_xh[node * (NH * F) + h * F + lane];
    float x2 = g_xh[node * (NH * F) + h * F + lane + 32];
    float s = fmaf(x1, as[h * F + lane], x2 * as[h * F + lane + 32]);
    float d = fmaf(x1, ad[h * F + lane], x2 * ad[h * F + lane + 32]);
    #pragma unroll
    for (int o = 16; o; o >>= 1) {
        s += __shfl_xor_sync(0xffffffffu, s, o);
        d += __shfl_xor_sync(0xffffffffu, d, o);
    }
    if (lane == 0) { g_asrc[node * NH + h] = s; g_adst[node * NH + h] = d; }
}

// segment max over edges + self loops; one thread per (item, head)
__global__ void k_emax(const int* __restrict__ src, const int* __restrict__ dst, int e, int n) {
    int t = blockIdx.x * blockDim.x + threadIdx.x;
    int i = t >> 2, h = t & 3;
    if (i >= e + n) return;
    int s = (i < e) ? src[i] : (i - e);
    int d = (i < e) ? dst[i] : (i - e);
    float ev = leaky(g_asrc[s * NH + h] + g_adst[d * NH + h], 0.2f);
    atomicMaxF(&g_emax[d * NH + h], ev);
}

// ex = exp(e - emax[dst]); denom scatter; stash ex
__global__ void k_den(const int* __restrict__ src, const int* __restrict__ dst, int e, int n) {
    int t = blockIdx.x * blockDim.x + threadIdx.x;
    int i = t >> 2, h = t & 3;
    if (i >= e + n) return;
    int s = (i < e) ? src[i] : (i - e);
    int d = (i < e) ? dst[i] : (i - e);
    float ev = leaky(g_asrc[s * NH + h] + g_adst[d * NH + h], 0.2f);
    float ex = expf(ev - g_emax[d * NH + h]);
    g_ex[i * NH + h] = ex;
    atomicAdd(&g_denom[d * NH + h], ex);
}

// out[dst,c] += (1/H) * sum_h alpha_h * xh[src,h,c]; one thread per (item, 4 features)
__global__ void k_scatter(const int* __restrict__ src, const int* __restrict__ dst,
                          float* __restrict__ out, int e, int n) {
    int t = blockIdx.x * blockDim.x + threadIdx.x;
    int i = t >> 4, q = (t & 15) << 2;
    if (i >= e + n) return;
    int s = (i < e) ? __ldg(&src[i]) : (i - e);
    int d = (i < e) ? __ldg(&dst[i]) : (i - e);
    float al[NH];
    #pragma unroll
    for (int h = 0; h < NH; h++)
        al[h] = g_ex[i * NH + h] / (g_denom[d * NH + h] + 1e-16f);
    float4 acc = make_float4(0.f, 0.f, 0.f, 0.f);
    #pragma unroll
    for (int h = 0; h < NH; h++) {
        const float4 v = *reinterpret_cast<const float4*>(g_xh + s * (NH * F) + h * F + q);
        acc.x = fmaf(al[h], v.x, acc.x);
        acc.y = fmaf(al[h], v.y, acc.y);
        acc.z = fmaf(al[h], v.z, acc.z);
        acc.w = fmaf(al[h], v.w, acc.w);
    }
    float* o = out + d * F + q;
    atomicAdd(o + 0, 0.25f * acc.x);
    atomicAdd(o + 1, 0.25f * acc.y);
    atomicAdd(o + 2, 0.25f * acc.z);
    atomicAdd(o + 3, 0.25f * acc.w);
}

__global__ void k_fin(float* __restrict__ out, const float* __restrict__ gb, int n) {
    int i = blockIdx.x * blockDim.x + threadIdx.x;
    if (i < n * F) {
        float v = out[i] + gb[i & 63];
        out[i] = leaky(v, 0.01f);
    }
}

// ---------------- launch ----------------
extern "C" void kernel_launch(void* const* d_in, const int* in_sizes, int n_in,
                              void* d_out, int out_size) {
    const float* x      = (const float*)d_in[0];
    const int*   ei     = (const int*)  d_in[1];
    const float* ea     = (const float*)d_in[2];
    const float* lng    = (const float*)d_in[3];
    const float* lnb    = (const float*)d_in[4];
    const float* cw     = (const float*)d_in[5];
    const float* cb     = (const float*)d_in[6];
    const float* gw     = (const float*)d_in[7];
    const float* as     = (const float*)d_in[8];
    const float* ad     = (const float*)d_in[9];
    const float* gb     = (const float*)d_in[10];
    float* out = (float*)d_out;

    const int n = in_sizes[0] / F;        // 50000
    const int e = in_sizes[2];            // 800000
    const int* src = ei;
    const int* dst = ei + e;

    const int TB = 256;
    auto cdiv = [](long long a, long long b) { return (int)((a + b - 1) / b); };

    k_init<<<cdiv((long long)n * F, TB), TB>>>(out, n);
    k_ln  <<<cdiv((long long)n * 32, TB), TB>>>(x, lng, lnb, n);
    k_deg <<<cdiv(e, TB), TB>>>(src, ea, e);
    k_dinv<<<cdiv(n, TB), TB>>>(n);
    k_we  <<<cdiv(e, TB), TB>>>(src, dst, ea, e);
    k_prop<<<cdiv((long long)e * 16, TB), TB>>>(src, dst, e, 0);
    k_prop<<<cdiv((long long)e * 16, TB), TB>>>(src, dst, e, 1);
    k_cheb<<<cdiv(n, 4), TB>>>(cw, cb, n);
    k_xw  <<<n, NH * F>>>(gw, n);
    k_att <<<n, NH * 32>>>(as, ad, n);
    k_emax<<<cdiv((long long)(e + n) * NH, TB), TB>>>(src, dst, e, n);
    k_den <<<cdiv((long long)(e + n) * NH, TB), TB>>>(src, dst, e, n);
    k_scatter<<<cdiv((long long)(e + n) * 16, TB), TB>>>(src, dst, out, e, n);
    k_fin <<<cdiv((long long)n * F, TB), TB>>>(out, gb, n);
}

// round 3
// speedup vs baseline: 1.3107x; 1.3107x over previous
#include <cuda_runtime.h>
#include <math.h>
#include <math_constants.h>

#define NMAX 50000
#define EMAX 800000
#define F 64
#define NH 4

// ---------------- scratch (device globals; referenced ONLY from device code) ----------------
__device__ float g_xln[NMAX * F];          // Tx0 (layernormed x)
__device__ float g_tx1[NMAX * F];          // Tx1 = L_hat @ Tx0
__device__ float g_tx2[NMAX * F];          // L_hat @ Tx1
__device__ float g_h[NMAX * F];            // cheb output after leaky
__device__ float g_xh[NMAX * NH * F];      // GAT projected features [N, H, C]
__device__ float g_asrc[NMAX * NH];
__device__ float g_adst[NMAX * NH];
__device__ float g_deg[NMAX];
__device__ float g_dinv[NMAX];
__device__ int   g_cnt[NMAX];              // in-degree counts (by dst)
__device__ int   g_rowptr[NMAX + 1];       // CSR row pointers (by dst)
__device__ int   g_cursor[NMAX];           // fill cursors
__device__ int   g_csrc[EMAX];             // CSR: src node per slot
__device__ float g_csw[EMAX];              // CSR: scaled-Laplacian weight per slot
__device__ float4 g_exn[EMAX];             // CSR: per-edge softmax numerators (4 heads)

__device__ __forceinline__ float leaky(float x, float s) {
    return x >= 0.f ? x : s * x;
}

// ---------------- kernels ----------------
__global__ void k_init(int n) {
    int i = blockIdx.x * blockDim.x + threadIdx.x;
    if (i < n) { g_deg[i] = 0.f; g_cnt[i] = 0; }
}

// one warp per node; lane handles c and c+32
__global__ void k_ln(const float* __restrict__ x, const float* __restrict__ gamma,
                     const float* __restrict__ beta, int n) {
    int warp = (blockIdx.x * blockDim.x + threadIdx.x) >> 5;
    int lane = threadIdx.x & 31;
    if (warp >= n) return;
    const float* xr = x + (size_t)warp * F;
    float a = xr[lane], b = xr[lane + 32];
    float s = a + b, sq = a * a + b * b;
    #pragma unroll
    for (int o = 16; o; o >>= 1) {
        s  += __shfl_xor_sync(0xffffffffu, s,  o);
        sq += __shfl_xor_sync(0xffffffffu, sq, o);
    }
    float mu  = s * (1.f / 64.f);
    float var = sq * (1.f / 64.f) - mu * mu;
    float r = rsqrtf(var + 1e-5f);
    g_xln[warp * F + lane]      = (a - mu) * r * gamma[lane]      + beta[lane];
    g_xln[warp * F + lane + 32] = (b - mu) * r * gamma[lane + 32] + beta[lane + 32];
}

// weighted out-degree by src (for sym norm) + in-degree count by dst (for CSR)
__global__ void k_degcnt(const int* __restrict__ src, const int* __restrict__ dst,
                         const float* __restrict__ ea, int e) {
    int i = blockIdx.x * blockDim.x + threadIdx.x;
    if (i >= e) return;
    atomicAdd(&g_deg[src[i]], ea[i]);
    atomicAdd(&g_cnt[dst[i]], 1);
}

__global__ void k_dinv(int n) {
    int i = blockIdx.x * blockDim.x + threadIdx.x;
    if (i < n) {
        float d = g_deg[i];
        g_dinv[i] = d > 0.f ? rsqrtf(d) : 0.f;
    }
}

// single-block exclusive scan of g_cnt -> g_rowptr / g_cursor
__global__ void k_scan(int n) {
    __shared__ int sm[1024];
    int t = threadIdx.x;
    int chunk = (n + 1023) >> 10;
    int b = t * chunk;
    int hi = min(b + chunk, n);
    int sum = 0;
    for (int i = b; i < hi; i++) sum += g_cnt[i];
    sm[t] = sum;
    __syncthreads();
    for (int o = 1; o < 1024; o <<= 1) {
        int v = (t >= o) ? sm[t - o] : 0;
        __syncthreads();
        if (t >= o) sm[t] += v;
        __syncthreads();
    }
    int run = (t == 0) ? 0 : sm[t - 1];
    for (int i = b; i < hi; i++) {
        g_rowptr[i] = run;
        g_cursor[i] = run;
        run += g_cnt[i];
    }
    if (t == 1023) g_rowptr[n] = run;
}

// scatter edges into CSR slots; compute Laplacian weight inline
__global__ void k_fill(const int* __restrict__ src, const int* __restrict__ dst,
                       const float* __restrict__ ea, int e) {
    int i = blockIdx.x * blockDim.x + threadIdx.x;
    if (i >= e) return;
    int s = src[i], d = dst[i];
    int pos = atomicAdd(&g_cursor[d], 1);
    g_csrc[pos] = s;
    g_csw[pos]  = -(g_dinv[s] * ea[i] * g_dinv[d]);
}

// gather-based propagation: out[node] = sum_j w_j * in[src_j]. warp per node.
__global__ void k_prop(int n, int phase) {
    int node = (blockIdx.x * blockDim.x + threadIdx.x) >> 5;
    int lane = threadIdx.x & 31;
    if (node >= n) return;
    const float* in = phase ? g_tx1 : g_xln;
    int beg = g_rowptr[node], end = g_rowptr[node + 1];
    float a0 = 0.f, a1 = 0.f;
    for (int j = beg; j < end; j++) {
        int s = g_csrc[j];
        float w = g_csw[j];
        a0 = fmaf(w, in[s * F + lane],      a0);
        a1 = fmaf(w, in[s * F + lane + 32], a1);
    }
    float* o = phase ? g_tx2 : g_tx1;
    o[node * F + lane]      = a0;
    o[node * F + lane + 32] = a1;
}

// Cheb combine: out = Tx0@W0 + Tx1@W1 + (2*Tx2 - Tx0)@W2 + b, leaky(0.01)
__global__ void k_cheb(const float* __restrict__ cw, const float* __restrict__ cb, int n) {
    int o = threadIdx.x & 63;
    int node = blockIdx.x * 4 + (threadIdx.x >> 6);
    if (node >= n) return;
    const float* t0 = g_xln + node * F;
    const float* t1 = g_tx1 + node * F;
    const float* t2 = g_tx2 + node * F;
    float acc = 0.f;
    #pragma unroll
    for (int c = 0; c < F; c++) {
        float a0 = t0[c], a1 = t1[c];
        float a2 = 2.f * t2[c] - a0;
        acc = fmaf(a0, cw[c * F + o], acc);
        acc = fmaf(a1, cw[F * F + c * F + o], acc);
        acc = fmaf(a2, cw[2 * F * F + c * F + o], acc);
    }
    acc += cb[o];
    g_h[node * F + o] = leaky(acc, 0.01f);
}

// xh = h @ gat_w  (64 -> 256). block = node, 256 threads.
__global__ void k_xw(const float* __restrict__ gw, int n) {
    int node = blockIdx.x;
    int j = threadIdx.x;
    const float* hr = g_h + node * F;
    float acc = 0.f;
    #pragma unroll
    for (int c = 0; c < F; c++)
        acc = fmaf(hr[c], gw[c * (NH * F) + j], acc);
    g_xh[node * (NH * F) + j] = acc;
}

// per-(node, head) attention dot products. block = node, 128 threads = 4 warps.
__global__ void k_att(const float* __restrict__ as, const float* __restrict__ ad, int n) {
    int node = blockIdx.x;
    int h = threadIdx.x >> 5, lane = threadIdx.x & 31;
    float x1 = g_xh[node * (NH * F) + h * F + lane];
    float x2 = g_xh[node * (NH * F) + h * F + lane + 32];
    float s = fmaf(x1, as[h * F + lane], x2 * as[h * F + lane + 32]);
    float d = fmaf(x1, ad[h * F + lane], x2 * ad[h * F + lane + 32]);
    #pragma unroll
    for (int o = 16; o; o >>= 1) {
        s += __shfl_xor_sync(0xffffffffu, s, o);
        d += __shfl_xor_sync(0xffffffffu, d, o);
    }
    if (lane == 0) { g_asrc[node * NH + h] = s; g_adst[node * NH + h] = d; }
}

// fused GAT: softmax over incoming edges + self loop, weighted aggregate,
// head mean, bias, leaky. one warp per node.
__global__ void k_gat(const float* __restrict__ gb, float* __restrict__ out, int n) {
    int node = (blockIdx.x * blockDim.x + threadIdx.x) >> 5;
    int lane = threadIdx.x & 31;
    if (node >= n) return;
    int beg = g_rowptr[node], end = g_rowptr[node + 1];

    float adst[NH], m[NH], selfev[NH];
    #pragma unroll
    for (int h = 0; h < NH; h++) {
        adst[h] = g_adst[node * NH + h];
        selfev[h] = leaky(g_asrc[node * NH + h] + adst[h], 0.2f);
        m[h] = selfev[h];
    }

    // pass A: max (lanes stride over edges)
    for (int j = beg + lane; j < end; j += 32) {
        int s = g_csrc[j];
        #pragma unroll
        for (int h = 0; h < NH; h++) {
            float ev = leaky(g_asrc[s * NH + h] + adst[h], 0.2f);
            m[h] = fmaxf(m[h], ev);
        }
    }
    #pragma unroll
    for (int o = 16; o; o >>= 1)
        #pragma unroll
        for (int h = 0; h < NH; h++)
            m[h] = fmaxf(m[h], __shfl_xor_sync(0xffffffffu, m[h], o));

    // pass B: exp-sum; stash numerators per CSR slot
    float den[NH] = {0.f, 0.f, 0.f, 0.f};
    for (int j = beg + lane; j < end; j += 32) {
        int s = g_csrc[j];
        float4 ex;
        float* exp_ = &ex.x;
        #pragma unroll
        for (int h = 0; h < NH; h++) {
            float ev = leaky(g_asrc[s * NH + h] + adst[h], 0.2f);
            float exv = __expf(ev - m[h]);
            exp_[h] = exv;
            den[h] += exv;
        }
        g_exn[j] = ex;
    }
    #pragma unroll
    for (int o = 16; o; o >>= 1)
        #pragma unroll
        for (int h = 0; h < NH; h++)
            den[h] += __shfl_xor_sync(0xffffffffu, den[h], o);
    float selfex[NH];
    #pragma unroll
    for (int h = 0; h < NH; h++) {
        selfex[h] = __expf(selfev[h] - m[h]);
        den[h] += selfex[h];
        den[h] += 1e-16f;
    }
    __syncwarp();

    // pass C: weighted feature gather (whole warp per edge; lanes = features)
    float acc[NH][2];
    #pragma unroll
    for (int h = 0; h < NH; h++) {
        const float* xr = g_xh + (size_t)node * (NH * F) + h * F;
        acc[h][0] = selfex[h] * xr[lane];
        acc[h][1] = selfex[h] * xr[lane + 32];
    }
    for (int j = beg; j < end; j++) {
        int s = g_csrc[j];                       // broadcast
        float4 ex = g_exn[j];                    // broadcast
        const float* xr = g_xh + (size_t)s * (NH * F);
        acc[0][0] = fmaf(ex.x, xr[lane],            acc[0][0]);
        acc[0][1] = fmaf(ex.x, xr[lane + 32],       acc[0][1]);
        acc[1][0] = fmaf(ex.y, xr[F + lane],        acc[1][0]);
        acc[1][1] = fmaf(ex.y, xr[F + lane + 32],   acc[1][1]);
        acc[2][0] = fmaf(ex.z, xr[2*F + lane],      acc[2][0]);
        acc[2][1] = fmaf(ex.z, xr[2*F + lane + 32], acc[2][1]);
        acc[3][0] = fmaf(ex.w, xr[3*F + lane],      acc[3][0]);
        acc[3][1] = fmaf(ex.w, xr[3*F + lane + 32], acc[3][1]);
    }

    float r0 = 0.25f * (acc[0][0] / den[0] + acc[1][0] / den[1] +
                        acc[2][0] / den[2] + acc[3][0] / den[3]);
    float r1 = 0.25f * (acc[0][1] / den[0] + acc[1][1] / den[1] +
                        acc[2][1] / den[2] + acc[3][1] / den[3]);
    out[node * F + lane]      = leaky(r0 + gb[lane],      0.01f);
    out[node * F + lane + 32] = leaky(r1 + gb[lane + 32], 0.01f);
}

// ---------------- launch ----------------
extern "C" void kernel_launch(void* const* d_in, const int* in_sizes, int n_in,
                              void* d_out, int out_size) {
    const float* x      = (const float*)d_in[0];
    const int*   ei     = (const int*)  d_in[1];
    const float* ea     = (const float*)d_in[2];
    const float* lng    = (const float*)d_in[3];
    const float* lnb    = (const float*)d_in[4];
    const float* cw     = (const float*)d_in[5];
    const float* cb     = (const float*)d_in[6];
    const float* gw     = (const float*)d_in[7];
    const float* as     = (const float*)d_in[8];
    const float* ad     = (const float*)d_in[9];
    const float* gb     = (const float*)d_in[10];
    float* out = (float*)d_out;

    const int n = in_sizes[0] / F;        // 50000
    const int e = in_sizes[2];            // 800000
    const int* src = ei;
    const int* dst = ei + e;

    const int TB = 256;
    auto cdiv = [](long long a, long long b) { return (int)((a + b - 1) / b); };

    k_init  <<<cdiv(n, TB), TB>>>(n);
    k_ln    <<<cdiv((long long)n * 32, TB), TB>>>(x, lng, lnb, n);
    k_degcnt<<<cdiv(e, TB), TB>>>(src, dst, ea, e);
    k_dinv  <<<cdiv(n, TB), TB>>>(n);
    k_scan  <<<1, 1024>>>(n);
    k_fill  <<<cdiv(e, TB), TB>>>(src, dst, ea, e);
    k_prop  <<<cdiv((long long)n * 32, TB), TB>>>(n, 0);
    k_prop  <<<cdiv((long long)n * 32, TB), TB>>>(n, 1);
    k_cheb  <<<cdiv(n, 4), TB>>>(cw, cb, n);
    k_xw    <<<n, NH * F>>>(gw, n);
    k_att   <<<n, NH * 32>>>(as, ad, n);
    k_gat   <<<cdiv((long long)n * 32, TB), TB>>>(gb, out, n);
}

// round 4
// speedup vs baseline: 2.4850x; 1.8960x over previous
#include <cuda_runtime.h>
#include <math.h>
#include <math_constants.h>

#define NMAX 50000
#define EMAX 800000
#define F 64
#define NH 4
#define NPB 8           // nodes per fused block

// ---------------- scratch (device globals; referenced ONLY from device code) ----------------
__device__ float g_xln[NMAX * F];          // Tx0 (layernormed x)
__device__ float g_tx1[NMAX * F];          // Tx1 = L_hat @ Tx0
__device__ float g_tx2[NMAX * F];          // L_hat @ Tx1
__device__ float g_xh[(size_t)NMAX * NH * F]; // GAT projected features [N, H, C]
__device__ float g_asrc[NMAX * NH];
__device__ float g_adst[NMAX * NH];
__device__ float g_deg[NMAX];
__device__ float g_dinv[NMAX];
__device__ int   g_cnt[NMAX];              // in-degree counts (by dst)
__device__ int   g_loc[NMAX];              // per-block local exclusive prefix
__device__ int   g_bsum[256];              // per-block sums -> exclusive offsets
__device__ int   g_rowptr[NMAX + 1];       // CSR row pointers (by dst)
__device__ int   g_cursor[NMAX];           // fill cursors
__device__ int   g_csrc[EMAX];             // CSR: src node per slot
__device__ float g_csw[EMAX];              // CSR: scaled-Laplacian weight per slot
__device__ float4 g_exn[EMAX];             // CSR: per-edge softmax numerators (4 heads)

__device__ __forceinline__ float leaky(float x, float s) {
    return x >= 0.f ? x : s * x;
}

// ---------------- kernels ----------------
__global__ void k_init(int n) {
    int i = blockIdx.x * blockDim.x + threadIdx.x;
    if (i < n) { g_deg[i] = 0.f; g_cnt[i] = 0; }
}

// one warp per node; lane handles c and c+32
__global__ void k_ln(const float* __restrict__ x, const float* __restrict__ gamma,
                     const float* __restrict__ beta, int n) {
    int warp = (blockIdx.x * blockDim.x + threadIdx.x) >> 5;
    int lane = threadIdx.x & 31;
    if (warp >= n) return;
    const float* xr = x + (size_t)warp * F;
    float a = xr[lane], b = xr[lane + 32];
    float s = a + b, sq = a * a + b * b;
    #pragma unroll
    for (int o = 16; o; o >>= 1) {
        s  += __shfl_xor_sync(0xffffffffu, s,  o);
        sq += __shfl_xor_sync(0xffffffffu, sq, o);
    }
    float mu  = s * (1.f / 64.f);
    float var = sq * (1.f / 64.f) - mu * mu;
    float r = rsqrtf(var + 1e-5f);
    g_xln[warp * F + lane]      = (a - mu) * r * gamma[lane]      + beta[lane];
    g_xln[warp * F + lane + 32] = (b - mu) * r * gamma[lane + 32] + beta[lane + 32];
}

// weighted out-degree by src + in-degree count by dst
__global__ void k_degcnt(const int* __restrict__ src, const int* __restrict__ dst,
                         const float* __restrict__ ea, int e) {
    int i = blockIdx.x * blockDim.x + threadIdx.x;
    if (i >= e) return;
    atomicAdd(&g_deg[src[i]], ea[i]);
    atomicAdd(&g_cnt[dst[i]], 1);
}

// ---- 3-phase parallel exclusive scan of g_cnt ----
__global__ void k_scan1(int n) {            // grid = ceil(n/256)
    __shared__ int sm[256];
    int t = threadIdx.x;
    int i = blockIdx.x * 256 + t;
    int v = (i < n) ? g_cnt[i] : 0;
    sm[t] = v;
    __syncthreads();
    for (int o = 1; o < 256; o <<= 1) {
        int u = (t >= o) ? sm[t - o] : 0;
        __syncthreads();
        sm[t] += u;
        __syncthreads();
    }
    if (i < n) g_loc[i] = sm[t] - v;        // exclusive within block
    if (t == 255) g_bsum[blockIdx.x] = sm[255];
}

__global__ void k_scan2(int nb) {           // 1 block, 256 threads; nb <= 256
    __shared__ int sm[256];
    int t = threadIdx.x;
    int v = (t < nb) ? g_bsum[t] : 0;
    sm[t] = v;
    __syncthreads();
    for (int o = 1; o < 256; o <<= 1) {
        int u = (t >= o) ? sm[t - o] : 0;
        __syncthreads();
        sm[t] += u;
        __syncthreads();
    }
    if (t < nb) g_bsum[t] = sm[t] - v;      // exclusive block offsets
}

__global__ void k_scan3(int n, int e) {     // rowptr/cursor/dinv
    int i = blockIdx.x * blockDim.x + threadIdx.x;
    if (i < n) {
        int r = g_bsum[i >> 8] + g_loc[i];
        g_rowptr[i] = r;
        g_cursor[i] = r;
        float d = g_deg[i];
        g_dinv[i] = d > 0.f ? rsqrtf(d) : 0.f;
    }
    if (i == 0) g_rowptr[n] = e;
}

// scatter edges into CSR slots; compute Laplacian weight inline
__global__ void k_fill(const int* __restrict__ src, const int* __restrict__ dst,
                       const float* __restrict__ ea, int e) {
    int i = blockIdx.x * blockDim.x + threadIdx.x;
    if (i >= e) return;
    int s = src[i], d = dst[i];
    int pos = atomicAdd(&g_cursor[d], 1);
    g_csrc[pos] = s;
    g_csw[pos]  = -(g_dinv[s] * ea[i] * g_dinv[d]);
}

// gather-based propagation: out[node] = sum_j w_j * in[src_j]; warp per node, 2-edge ILP
__global__ void k_prop(int n, int phase) {
    int node = (blockIdx.x * blockDim.x + threadIdx.x) >> 5;
    int lane = threadIdx.x & 31;
    if (node >= n) return;
    const float* in = phase ? g_tx1 : g_xln;
    int beg = g_rowptr[node], end = g_rowptr[node + 1];
    float a0 = 0.f, a1 = 0.f, b0 = 0.f, b1 = 0.f;
    int j = beg;
    for (; j + 2 <= end; j += 2) {
        int   s0 = __ldg(&g_csrc[j]),  s1 = __ldg(&g_csrc[j + 1]);
        float w0 = __ldg(&g_csw[j]),   w1 = __ldg(&g_csw[j + 1]);
        const float* r0 = in + s0 * F;
        const float* r1 = in + s1 * F;
        a0 = fmaf(w0, r0[lane],      a0);
        a1 = fmaf(w0, r0[lane + 32], a1);
        b0 = fmaf(w1, r1[lane],      b0);
        b1 = fmaf(w1, r1[lane + 32], b1);
    }
    if (j < end) {
        int s0 = g_csrc[j]; float w0 = g_csw[j];
        const float* r0 = in + s0 * F;
        a0 = fmaf(w0, r0[lane],      a0);
        a1 = fmaf(w0, r0[lane + 32], a1);
    }
    float* ou = phase ? g_tx2 : g_tx1;
    ou[node * F + lane]      = a0 + b0;
    ou[node * F + lane + 32] = a1 + b1;
}

// fused Cheb-combine + GAT projection + attention dots. 8 nodes per 256-thread block.
__global__ void k_fused(const float* __restrict__ cw, const float* __restrict__ cb,
                        const float* __restrict__ gw, const float* __restrict__ as,
                        const float* __restrict__ ad, int n) {
    __shared__ float s_in[NPB][3][F];     // 6KB
    __shared__ float s_h[NPB][F];         // 2KB
    __shared__ float s_red[2][8][NPB];    // [src/dst][warp][node]
    int t = threadIdx.x;
    int base = blockIdx.x * NPB;

    for (int i = t; i < NPB * F; i += 256) {
        int m = i >> 6, c = i & 63;
        int node = base + m;
        if (node < n) {
            s_in[m][0][c] = g_xln[node * F + c];
            s_in[m][1][c] = g_tx1[node * F + c];
            s_in[m][2][c] = g_tx2[node * F + c];
        }
    }
    __syncthreads();

    // Cheb: thread computes output o for nodes mA = t>>6 and mB = mA+4
    int o = t & 63, mA = t >> 6, mB = mA + 4;
    float accA = 0.f, accB = 0.f;
    #pragma unroll 8
    for (int c = 0; c < F; c++) {
        float w0 = cw[c * F + o];
        float w1 = cw[F * F + c * F + o];
        float w2 = cw[2 * F * F + c * F + o];
        float a0 = s_in[mA][0][c], a1 = s_in[mA][1][c];
        float a2 = 2.f * s_in[mA][2][c] - a0;
        accA = fmaf(a0, w0, fmaf(a1, w1, fmaf(a2, w2, accA)));
        float b0 = s_in[mB][0][c], b1 = s_in[mB][1][c];
        float b2 = 2.f * s_in[mB][2][c] - b0;
        accB = fmaf(b0, w0, fmaf(b1, w1, fmaf(b2, w2, accB)));
    }
    float bias = cb[o];
    s_h[mA][o] = leaky(accA + bias, 0.01f);
    s_h[mB][o] = leaky(accB + bias, 0.01f);
    __syncthreads();

    // xw: thread computes output column j = t for all 8 nodes
    int j = t;
    float acc[NPB];
    #pragma unroll
    for (int m = 0; m < NPB; m++) acc[m] = 0.f;
    #pragma unroll 4
    for (int c4 = 0; c4 < F / 4; c4++) {
        float w0 = gw[(c4 * 4 + 0) * 256 + j];
        float w1 = gw[(c4 * 4 + 1) * 256 + j];
        float w2 = gw[(c4 * 4 + 2) * 256 + j];
        float w3 = gw[(c4 * 4 + 3) * 256 + j];
        #pragma unroll
        for (int m = 0; m < NPB; m++) {
            float4 hv = *reinterpret_cast<const float4*>(&s_h[m][c4 * 4]);
            acc[m] = fmaf(hv.x, w0, fmaf(hv.y, w1, fmaf(hv.z, w2, fmaf(hv.w, w3, acc[m]))));
        }
    }
    #pragma unroll
    for (int m = 0; m < NPB; m++) {
        int node = base + m;
        if (node < n) g_xh[(size_t)node * 256 + j] = acc[m];
    }

    // attention dots: head = j>>6; warps 2h, 2h+1 cover head h
    float asj = as[j], adj = ad[j];
    int lane = t & 31, wid = t >> 5;
    #pragma unroll
    for (int m = 0; m < NPB; m++) {
        float sv = acc[m] * asj, dv = acc[m] * adj;
        #pragma unroll
        for (int off = 16; off; off >>= 1) {
            sv += __shfl_xor_sync(0xffffffffu, sv, off);
            dv += __shfl_xor_sync(0xffffffffu, dv, off);
        }
        if (lane == 0) { s_red[0][wid][m] = sv; s_red[1][wid][m] = dv; }
    }
    __syncthreads();
    if (t < 32) {
        int h = t >> 3, m = t & 7;
        int node = base + m;
        if (node < n) {
            g_asrc[node * NH + h] = s_red[0][2 * h][m] + s_red[0][2 * h + 1][m];
            g_adst[node * NH + h] = s_red[1][2 * h][m] + s_red[1][2 * h + 1][m];
        }
    }
}

// fused GAT: softmax + aggregate + head-mean + bias + leaky. one warp per node.
__global__ void k_gat(const float* __restrict__ gb, float* __restrict__ out, int n) {
    int node = (blockIdx.x * blockDim.x + threadIdx.x) >> 5;
    int lane = threadIdx.x & 31;
    if (node >= n) return;
    int beg = g_rowptr[node], end = g_rowptr[node + 1];

    const float4* pa = reinterpret_cast<const float4*>(g_asrc);
    const float4* pd = reinterpret_cast<const float4*>(g_adst);
    float4 adv = pd[node];
    float adst[NH] = {adv.x, adv.y, adv.z, adv.w};
    float4 asn = pa[node];
    float asf[NH] = {asn.x, asn.y, asn.z, asn.w};
    float m[NH], selfev[NH];
    #pragma unroll
    for (int h = 0; h < NH; h++) {
        selfev[h] = leaky(asf[h] + adst[h], 0.2f);
        m[h] = selfev[h];
    }

    // pass A: max (lanes stride over edges)
    for (int j = beg + lane; j < end; j += 32) {
        int s = g_csrc[j];
        float4 av = pa[s];
        float a4[NH] = {av.x, av.y, av.z, av.w};
        #pragma unroll
        for (int h = 0; h < NH; h++)
            m[h] = fmaxf(m[h], leaky(a4[h] + adst[h], 0.2f));
    }
    #pragma unroll
    for (int o = 16; o; o >>= 1)
        #pragma unroll
        for (int h = 0; h < NH; h++)
            m[h] = fmaxf(m[h], __shfl_xor_sync(0xffffffffu, m[h], o));

    // pass B: exp-sum; stash numerators per CSR slot
    float den[NH] = {0.f, 0.f, 0.f, 0.f};
    for (int j = beg + lane; j < end; j += 32) {
        int s = g_csrc[j];
        float4 av = pa[s];
        float a4[NH] = {av.x, av.y, av.z, av.w};
        float4 ex;
        float* exp_ = &ex.x;
        #pragma unroll
        for (int h = 0; h < NH; h++) {
            float exv = __expf(leaky(a4[h] + adst[h], 0.2f) - m[h]);
            exp_[h] = exv;
            den[h] += exv;
        }
        g_exn[j] = ex;
    }
    #pragma unroll
    for (int o = 16; o; o >>= 1)
        #pragma unroll
        for (int h = 0; h < NH; h++)
            den[h] += __shfl_xor_sync(0xffffffffu, den[h], o);
    float selfex[NH];
    #pragma unroll
    for (int h = 0; h < NH; h++) {
        selfex[h] = __expf(selfev[h] - m[h]);
        den[h] += selfex[h] + 1e-16f;
    }
    __syncwarp();

    // pass C: weighted feature gather (warp per edge; lanes = features), 2-edge ILP
    float acc[NH][2];
    #pragma unroll
    for (int h = 0; h < NH; h++) {
        const float* xr = g_xh + (size_t)node * (NH * F) + h * F;
        acc[h][0] = selfex[h] * xr[lane];
        acc[h][1] = selfex[h] * xr[lane + 32];
    }
    int j = beg;
    for (; j + 2 <= end; j += 2) {
        int s0 = g_csrc[j], s1 = g_csrc[j + 1];
        float4 e0 = g_exn[j], e1 = g_exn[j + 1];
        const float* x0 = g_xh + (size_t)s0 * (NH * F);
        const float* x1 = g_xh + (size_t)s1 * (NH * F);
        acc[0][0] = fmaf(e0.x, x0[lane],            acc[0][0]);
        acc[0][1] = fmaf(e0.x, x0[lane + 32],       acc[0][1]);
        acc[1][0] = fmaf(e0.y, x0[F + lane],        acc[1][0]);
        acc[1][1] = fmaf(e0.y, x0[F + lane + 32],   acc[1][1]);
        acc[2][0] = fmaf(e0.z, x0[2*F + lane],      acc[2][0]);
        acc[2][1] = fmaf(e0.z, x0[2*F + lane + 32], acc[2][1]);
        acc[3][0] = fmaf(e0.w, x0[3*F + lane],      acc[3][0]);
        acc[3][1] = fmaf(e0.w, x0[3*F + lane + 32], acc[3][1]);
        acc[0][0] = fmaf(e1.x, x1[lane],            acc[0][0]);
        acc[0][1] = fmaf(e1.x, x1[lane + 32],       acc[0][1]);
        acc[1][0] = fmaf(e1.y, x1[F + lane],        acc[1][0]);
        acc[1][1] = fmaf(e1.y, x1[F + lane + 32],   acc[1][1]);
        acc[2][0] = fmaf(e1.z, x1[2*F + lane],      acc[2][0]);
        acc[2][1] = fmaf(e1.z, x1[2*F + lane + 32], acc[2][1]);
        acc[3][0] = fmaf(e1.w, x1[3*F + lane],      acc[3][0]);
        acc[3][1] = fmaf(e1.w, x1[3*F + lane + 32], acc[3][1]);
    }
    if (j < end) {
        int s0 = g_csrc[j];
        float4 e0 = g_exn[j];
        const float* x0 = g_xh + (size_t)s0 * (NH * F);
        acc[0][0] = fmaf(e0.x, x0[lane],            acc[0][0]);
        acc[0][1] = fmaf(e0.x, x0[lane + 32],       acc[0][1]);
        acc[1][0] = fmaf(e0.y, x0[F + lane],        acc[1][0]);
        acc[1][1] = fmaf(e0.y, x0[F + lane + 32],   acc[1][1]);
        acc[2][0] = fmaf(e0.z, x0[2*F + lane],      acc[2][0]);
        acc[2][1] = fmaf(e0.z, x0[2*F + lane + 32], acc[2][1]);
        acc[3][0] = fmaf(e0.w, x0[3*F + lane],      acc[3][0]);
        acc[3][1] = fmaf(e0.w, x0[3*F + lane + 32], acc[3][1]);
    }

    float i0 = 1.f / den[0], i1 = 1.f / den[1], i2 = 1.f / den[2], i3 = 1.f / den[3];
    float r0 = 0.25f * (acc[0][0] * i0 + acc[1][0] * i1 + acc[2][0] * i2 + acc[3][0] * i3);
    float r1 = 0.25f * (acc[0][1] * i0 + acc[1][1] * i1 + acc[2][1] * i2 + acc[3][1] * i3);
    out[node * F + lane]      = leaky(r0 + gb[lane],      0.01f);
    out[node * F + lane + 32] = leaky(r1 + gb[lane + 32], 0.01f);
}

// ---------------- launch ----------------
extern "C" void kernel_launch(void* const* d_in, const int* in_sizes, int n_in,
                              void* d_out, int out_size) {
    const float* x      = (const float*)d_in[0];
    const int*   ei     = (const int*)  d_in[1];
    const float* ea     = (const float*)d_in[2];
    const float* lng    = (const float*)d_in[3];
    const float* lnb    = (const float*)d_in[4];
    const float* cw     = (const float*)d_in[5];
    const float* cb     = (const float*)d_in[6];
    const float* gw     = (const float*)d_in[7];
    const float* as     = (const float*)d_in[8];
    const float* ad     = (const float*)d_in[9];
    const float* gb     = (const float*)d_in[10];
    float* out = (float*)d_out;

    const int n = in_sizes[0] / F;        // 50000
    const int e = in_sizes[2];            // 800000
    const int* src = ei;
    const int* dst = ei + e;

    const int TB = 256;
    auto cdiv = [](long long a, long long b) { return (int)((a + b - 1) / b); };
    int nb = cdiv(n, 256);

    k_init  <<<cdiv(n, TB), TB>>>(n);
    k_ln    <<<cdiv((long long)n * 32, TB), TB>>>(x, lng, lnb, n);
    k_degcnt<<<cdiv(e, TB), TB>>>(src, dst, ea, e);
    k_scan1 <<<nb, 256>>>(n);
    k_scan2 <<<1, 256>>>(nb);
    k_scan3 <<<cdiv(n, TB), TB>>>(n, e);
    k_fill  <<<cdiv(e, TB), TB>>>(src, dst, ea, e);
    k_prop  <<<cdiv((long long)n * 32, TB), TB>>>(n, 0);
    k_prop  <<<cdiv((long long)n * 32, TB), TB>>>(n, 1);
    k_fused <<<cdiv(n, NPB), 256>>>(cw, cb, gw, as, ad, n);
    k_gat   <<<cdiv((long long)n * 32, TB), TB>>>(gb, out, n);
}

// round 5
// speedup vs baseline: 2.8942x; 1.1646x over previous
#include <cuda_runtime.h>
#include <cuda_fp16.h>
#include <math.h>
#include <math_constants.h>

#define NMAX 50000
#define EMAX 800000
#define F 64
#define NH 4
#define NPB 16          // nodes per fused block

// ---------------- scratch (device globals; referenced ONLY from device code) ----------------
__device__ float   g_xln[NMAX * F];           // Tx0 (layernormed x)
__device__ float   g_tx1[NMAX * F];           // Tx1 = L_hat @ Tx0
__device__ float   g_tx2[NMAX * F];           // L_hat @ Tx1
__device__ __half2 g_xh16[(size_t)NMAX * 128];// projected features, [node][head][feat/2]
__device__ float   g_asrc[NMAX * NH];
__device__ float   g_adst[NMAX * NH];
__device__ float   g_deg[NMAX];
__device__ float   g_dinv[NMAX];
__device__ int     g_cnt[NMAX];               // in-degree counts (by dst)
__device__ int     g_loc[NMAX];               // per-block local exclusive prefix
__device__ int     g_bsum[256];               // per-block sums -> exclusive offsets
__device__ int     g_rowptr[NMAX + 1];        // CSR row pointers (by dst)
__device__ int     g_cursor[NMAX];            // fill cursors
__device__ int2    g_cse[EMAX];               // CSR: (src, weight-as-int) per slot

__device__ __forceinline__ float leaky(float x, float s) {
    return x >= 0.f ? x : s * x;
}

// ---------------- kernels ----------------
__global__ void k_init(int n) {
    int i = blockIdx.x * blockDim.x + threadIdx.x;
    if (i < n) { g_deg[i] = 0.f; g_cnt[i] = 0; }
}

// one warp per node; lane handles c and c+32
__global__ void k_ln(const float* __restrict__ x, const float* __restrict__ gamma,
                     const float* __restrict__ beta, int n) {
    int warp = (blockIdx.x * blockDim.x + threadIdx.x) >> 5;
    int lane = threadIdx.x & 31;
    if (warp >= n) return;
    const float* xr = x + (size_t)warp * F;
    float a = xr[lane], b = xr[lane + 32];
    float s = a + b, sq = a * a + b * b;
    #pragma unroll
    for (int o = 16; o; o >>= 1) {
        s  += __shfl_xor_sync(0xffffffffu, s,  o);
        sq += __shfl_xor_sync(0xffffffffu, sq, o);
    }
    float mu  = s * (1.f / 64.f);
    float var = sq * (1.f / 64.f) - mu * mu;
    float r = rsqrtf(var + 1e-5f);
    g_xln[warp * F + lane]      = (a - mu) * r * gamma[lane]      + beta[lane];
    g_xln[warp * F + lane + 32] = (b - mu) * r * gamma[lane + 32] + beta[lane + 32];
}

// weighted out-degree by src + in-degree count by dst
__global__ void k_degcnt(const int* __restrict__ src, const int* __restrict__ dst,
                         const float* __restrict__ ea, int e) {
    int i = blockIdx.x * blockDim.x + threadIdx.x;
    if (i >= e) return;
    atomicAdd(&g_deg[src[i]], ea[i]);
    atomicAdd(&g_cnt[dst[i]], 1);
}

// ---- 3-phase parallel exclusive scan of g_cnt ----
__global__ void k_scan1(int n) {            // grid = ceil(n/256)
    __shared__ int sm[256];
    int t = threadIdx.x;
    int i = blockIdx.x * 256 + t;
    int v = (i < n) ? g_cnt[i] : 0;
    sm[t] = v;
    __syncthreads();
    for (int o = 1; o < 256; o <<= 1) {
        int u = (t >= o) ? sm[t - o] : 0;
        __syncthreads();
        sm[t] += u;
        __syncthreads();
    }
    if (i < n) g_loc[i] = sm[t] - v;
    if (t == 255) g_bsum[blockIdx.x] = sm[255];
}

__global__ void k_scan2(int nb) {           // 1 block, 256 threads; nb <= 256
    __shared__ int sm[256];
    int t = threadIdx.x;
    int v = (t < nb) ? g_bsum[t] : 0;
    sm[t] = v;
    __syncthreads();
    for (int o = 1; o < 256; o <<= 1) {
        int u = (t >= o) ? sm[t - o] : 0;
        __syncthreads();
        sm[t] += u;
        __syncthreads();
    }
    if (t < nb) g_bsum[t] = sm[t] - v;
}

__global__ void k_scan3(int n, int e) {     // rowptr/cursor/dinv
    int i = blockIdx.x * blockDim.x + threadIdx.x;
    if (i < n) {
        int r = g_bsum[i >> 8] + g_loc[i];
        g_rowptr[i] = r;
        g_cursor[i] = r;
        float d = g_deg[i];
        g_dinv[i] = d > 0.f ? rsqrtf(d) : 0.f;
    }
    if (i == 0) g_rowptr[n] = e;
}

// scatter edges into CSR slots; compute Laplacian weight inline (one int2 store)
__global__ void k_fill(const int* __restrict__ src, const int* __restrict__ dst,
                       const float* __restrict__ ea, int e) {
    int i = blockIdx.x * blockDim.x + threadIdx.x;
    if (i >= e) return;
    int s = src[i], d = dst[i];
    int pos = atomicAdd(&g_cursor[d], 1);
    float w = -(g_dinv[s] * ea[i] * g_dinv[d]);
    g_cse[pos] = make_int2(s, __float_as_int(w));
}

// gather-based propagation: out[node] = sum_j w_j * in[src_j]; warp per node, 2-edge ILP
__global__ void k_prop(int n, int phase) {
    int node = (blockIdx.x * blockDim.x + threadIdx.x) >> 5;
    int lane = threadIdx.x & 31;
    if (node >= n) return;
    const float* in = phase ? g_tx1 : g_xln;
    int beg = g_rowptr[node], end = g_rowptr[node + 1];
    float a0 = 0.f, a1 = 0.f, b0 = 0.f, b1 = 0.f;
    int j = beg;
    for (; j + 2 <= end; j += 2) {
        int2 e0 = __ldg(&g_cse[j]), e1 = __ldg(&g_cse[j + 1]);
        float w0 = __int_as_float(e0.y), w1 = __int_as_float(e1.y);
        const float* r0 = in + e0.x * F;
        const float* r1 = in + e1.x * F;
        a0 = fmaf(w0, r0[lane],      a0);
        a1 = fmaf(w0, r0[lane + 32], a1);
        b0 = fmaf(w1, r1[lane],      b0);
        b1 = fmaf(w1, r1[lane + 32], b1);
    }
    if (j < end) {
        int2 e0 = g_cse[j];
        float w0 = __int_as_float(e0.y);
        const float* r0 = in + e0.x * F;
        a0 = fmaf(w0, r0[lane],      a0);
        a1 = fmaf(w0, r0[lane + 32], a1);
    }
    float* ou = phase ? g_tx2 : g_tx1;
    ou[node * F + lane]      = a0 + b0;
    ou[node * F + lane + 32] = a1 + b1;
}

// fused Cheb-combine + GAT projection + attention dots. 16 nodes per 256-thread block.
__global__ void k_fused(const float* __restrict__ cw, const float* __restrict__ cb,
                        const float* __restrict__ gw, const float* __restrict__ as,
                        const float* __restrict__ ad, int n) {
    __shared__ float s_in[NPB][3][F];     // 12KB
    __shared__ float s_h[NPB][F];         // 4KB
    __shared__ float s_red[2][8][NPB];    // 1KB
    int t = threadIdx.x;
    int base = blockIdx.x * NPB;

    for (int i = t; i < NPB * F; i += 256) {
        int m = i >> 6, c = i & 63;
        int node = base + m;
        if (node < n) {
            s_in[m][0][c] = g_xln[node * F + c];
            s_in[m][1][c] = g_tx1[node * F + c];
            s_in[m][2][c] = g_tx2[node * F + c];
        }
    }
    __syncthreads();

    // Cheb: thread handles output column o for nodes m = g, g+4, g+8, g+12
    int o = t & 63, g = t >> 6;
    float accc[4] = {0.f, 0.f, 0.f, 0.f};
    #pragma unroll 8
    for (int c = 0; c < F; c++) {
        float w0 = cw[c * F + o];
        float w1 = cw[F * F + c * F + o];
        float w2 = cw[2 * F * F + c * F + o];
        #pragma unroll
        for (int q = 0; q < 4; q++) {
            int m = g + 4 * q;
            float a0 = s_in[m][0][c], a1 = s_in[m][1][c];
            float a2 = 2.f * s_in[m][2][c] - a0;
            accc[q] = fmaf(a0, w0, fmaf(a1, w1, fmaf(a2, w2, accc[q])));
        }
    }
    float bias = cb[o];
    #pragma unroll
    for (int q = 0; q < 4; q++)
        s_h[g + 4 * q][o] = leaky(accc[q] + bias, 0.01f);
    __syncthreads();

    // xw: thread computes output column j = t (head j>>6, feature j&63) for all 16 nodes
    int j = t;
    float acc[NPB];
    #pragma unroll
    for (int m = 0; m < NPB; m++) acc[m] = 0.f;
    #pragma unroll 4
    for (int c4 = 0; c4 < F / 4; c4++) {
        float w0 = gw[(c4 * 4 + 0) * 256 + j];
        float w1 = gw[(c4 * 4 + 1) * 256 + j];
        float w2 = gw[(c4 * 4 + 2) * 256 + j];
        float w3 = gw[(c4 * 4 + 3) * 256 + j];
        #pragma unroll
        for (int m = 0; m < NPB; m++) {
            float4 hv = *reinterpret_cast<const float4*>(&s_h[m][c4 * 4]);
            acc[m] = fmaf(hv.x, w0, fmaf(hv.y, w1, fmaf(hv.z, w2, fmaf(hv.w, w3, acc[m]))));
        }
    }

    // write xh as half2 (features 2c', 2c'+1 packed): even-feature threads store
    int c = t & 63, h = t >> 6;
    #pragma unroll
    for (int m = 0; m < NPB; m++) {
        float other = __shfl_xor_sync(0xffffffffu, acc[m], 1);
        int node = base + m;
        if (!(c & 1) && node < n) {
            __half2 hv = __floats2half2_rn(acc[m], other);
            g_xh16[(size_t)node * 128 + h * 32 + (c >> 1)] = hv;
        }
    }

    // attention dots
    float asj = as[j], adj = ad[j];
    int lane = t & 31, wid = t >> 5;
    #pragma unroll
    for (int m = 0; m < NPB; m++) {
        float sv = acc[m] * asj, dv = acc[m] * adj;
        #pragma unroll
        for (int off = 16; off; off >>= 1) {
            sv += __shfl_xor_sync(0xffffffffu, sv, off);
            dv += __shfl_xor_sync(0xffffffffu, dv, off);
        }
        if (lane == 0) { s_red[0][wid][m] = sv; s_red[1][wid][m] = dv; }
    }
    __syncthreads();
    if (t < 64) {
        int hh = t >> 4, m = t & 15;
        int node = base + m;
        if (node < n) {
            g_asrc[node * NH + hh] = s_red[0][2 * hh][m] + s_red[0][2 * hh + 1][m];
            g_adst[node * NH + hh] = s_red[1][2 * hh][m] + s_red[1][2 * hh + 1][m];
        }
    }
}

// fused GAT, single edge sweep, no max subtraction (logits bounded).
// warp per node; chunks of 32 edges: lanes compute exp, then warp gathers features.
__global__ void k_gat(const float* __restrict__ gb, float* __restrict__ out, int n) {
    __shared__ float4 s_ex[8][32];
    __shared__ int    s_s[8][32];
    int wid = threadIdx.x >> 5;
    int node = (blockIdx.x * blockDim.x + threadIdx.x) >> 5;
    int lane = threadIdx.x & 31;
    if (node >= n) return;
    int beg = g_rowptr[node], end = g_rowptr[node + 1];

    const float4* pa = reinterpret_cast<const float4*>(g_asrc);
    const float4* pd = reinterpret_cast<const float4*>(g_adst);
    float4 adv = pd[node];
    float4 asn = pa[node];
    float selfex[NH];
    selfex[0] = __expf(leaky(asn.x + adv.x, 0.2f));
    selfex[1] = __expf(leaky(asn.y + adv.y, 0.2f));
    selfex[2] = __expf(leaky(asn.z + adv.z, 0.2f));
    selfex[3] = __expf(leaky(asn.w + adv.w, 0.2f));

    // accumulators: per lane, features (2*lane, 2*lane+1) for each head
    const __half2* xh = g_xh16;
    float2 acc[NH];
    #pragma unroll
    for (int h = 0; h < NH; h++) {
        float2 f = __half22float2(xh[(size_t)node * 128 + h * 32 + lane]);
        acc[h] = make_float2(selfex[h] * f.x, selfex[h] * f.y);
    }
    float den[NH] = {0.f, 0.f, 0.f, 0.f};   // lane-partial; self added after reduce

    for (int j0 = beg; j0 < end; j0 += 32) {
        int cnt = min(32, end - j0);
        float4 ex = make_float4(0.f, 0.f, 0.f, 0.f);
        int s = 0;
        if (lane < cnt) {
            s = g_cse[j0 + lane].x;
            float4 av = pa[s];
            ex.x = __expf(leaky(av.x + adv.x, 0.2f));
            ex.y = __expf(leaky(av.y + adv.y, 0.2f));
            ex.z = __expf(leaky(av.z + adv.z, 0.2f));
            ex.w = __expf(leaky(av.w + adv.w, 0.2f));
            den[0] += ex.x; den[1] += ex.y; den[2] += ex.z; den[3] += ex.w;
        }
        s_ex[wid][lane] = ex;
        s_s[wid][lane] = s;
        __syncwarp();
        #pragma unroll 4
        for (int k = 0; k < cnt; k++) {
            int sk = s_s[wid][k];
            float4 exk = s_ex[wid][k];
            const __half2* xr = xh + (size_t)sk * 128;
            float2 f0 = __half22float2(xr[lane]);
            float2 f1 = __half22float2(xr[32 + lane]);
            float2 f2 = __half22float2(xr[64 + lane]);
            float2 f3 = __half22float2(xr[96 + lane]);
            acc[0].x = fmaf(exk.x, f0.x, acc[0].x); acc[0].y = fmaf(exk.x, f0.y, acc[0].y);
            acc[1].x = fmaf(exk.y, f1.x, acc[1].x); acc[1].y = fmaf(exk.y, f1.y, acc[1].y);
            acc[2].x = fmaf(exk.z, f2.x, acc[2].x); acc[2].y = fmaf(exk.z, f2.y, acc[2].y);
            acc[3].x = fmaf(exk.w, f3.x, acc[3].x); acc[3].y = fmaf(exk.w, f3.y, acc[3].y);
        }
        __syncwarp();
    }

    #pragma unroll
    for (int o = 16; o; o >>= 1)
        #pragma unroll
        for (int h = 0; h < NH; h++)
            den[h] += __shfl_xor_sync(0xffffffffu, den[h], o);
    float iv[NH];
    #pragma unroll
    for (int h = 0; h < NH; h++)
        iv[h] = 1.f / (den[h] + selfex[h] + 1e-16f);

    float r0 = 0.25f * (acc[0].x * iv[0] + acc[1].x * iv[1] + acc[2].x * iv[2] + acc[3].x * iv[3]);
    float r1 = 0.25f * (acc[0].y * iv[0] + acc[1].y * iv[1] + acc[2].y * iv[2] + acc[3].y * iv[3]);
    float2 res;
    res.x = leaky(r0 + gb[2 * lane],     0.01f);
    res.y = leaky(r1 + gb[2 * lane + 1], 0.01f);
    *reinterpret_cast<float2*>(out + (size_t)node * F + 2 * lane) = res;
}

// ---------------- launch ----------------
extern "C" void kernel_launch(void* const* d_in, const int* in_sizes, int n_in,
                              void* d_out, int out_size) {
    const float* x      = (const float*)d_in[0];
    const int*   ei     = (const int*)  d_in[1];
    const float* ea     = (const float*)d_in[2];
    const float* lng    = (const float*)d_in[3];
    const float* lnb    = (const float*)d_in[4];
    const float* cw     = (const float*)d_in[5];
    const float* cb     = (const float*)d_in[6];
    const float* gw     = (const float*)d_in[7];
    const float* as     = (const float*)d_in[8];
    const float* ad     = (const float*)d_in[9];
    const float* gb     = (const float*)d_in[10];
    float* out = (float*)d_out;

    const int n = in_sizes[0] / F;        // 50000
    const int e = in_sizes[2];            // 800000
    const int* src = ei;
    const int* dst = ei + e;

    const int TB = 256;
    auto cdiv = [](long long a, long long b) { return (int)((a + b - 1) / b); };
    int nb = cdiv(n, 256);

    k_init  <<<cdiv(n, TB), TB>>>(n);
    k_ln    <<<cdiv((long long)n * 32, TB), TB>>>(x, lng, lnb, n);
    k_degcnt<<<cdiv(e, TB), TB>>>(src, dst, ea, e);
    k_scan1 <<<nb, 256>>>(n);
    k_scan2 <<<1, 256>>>(nb);
    k_scan3 <<<cdiv(n, TB), TB>>>(n, e);
    k_fill  <<<cdiv(e, TB), TB>>>(src, dst, ea, e);
    k_prop  <<<cdiv((long long)n * 32, TB), TB>>>(n, 0);
    k_prop  <<<cdiv((long long)n * 32, TB), TB>>>(n, 1);
    k_fused <<<cdiv(n, NPB), 256>>>(cw, cb, gw, as, ad, n);
    k_gat   <<<cdiv((long long)n * 32, TB), TB>>>(gb, out, n);
}